// round 4
// baseline (speedup 1.0000x reference)
#include <cuda_runtime.h>
#include <cuda_bf16.h>
#include <cstdint>
#include <math.h>

#define HD 1024
#define NS 65536
#define BS 2048
#define TOPK 8
#define MCAND 32
#define NBLK (NS / 128)          // 512 n-blocks
#define PART_PER_BLK 16          // two 64-col halves x top-8

// ---------------- device scratch (static, allocation-free) ----------------
__device__ float         g_colmax[HD];
__device__ float         g_scale[HD];
__device__ float         g_invn[NS];
__device__ __nv_bfloat16 g_an_bf[(size_t)NS * HD];     // 128 MB bf16 normalized addresses
__device__ float         g_query[(size_t)BS * HD];
__device__ float         g_qn[(size_t)BS * HD];
__device__ __nv_bfloat16 g_qn_bf[(size_t)BS * HD];
__device__ float         g_pv[(size_t)BS * NBLK * PART_PER_BLK];  // 67 MB partial top vals
__device__ int           g_pi[(size_t)BS * NBLK * PART_PER_BLK];  // 67 MB partial top idx
__device__ int           g_cand[BS * MCAND];
__device__ float         g_read[(size_t)BS * HD];

__device__ __forceinline__ void cp16(uint32_t smem, const void* gmem) {
    asm volatile("cp.async.cg.shared.global [%0], [%1], 16;\n" :: "r"(smem), "l"(gmem));
}
#define CP_COMMIT() asm volatile("cp.async.commit_group;\n" ::: "memory")
#define CP_WAIT(n)  asm volatile("cp.async.wait_group %0;\n" :: "n"(n) : "memory")

// ---------------- per-column |max| of contents -> int8 scale ----------------
__global__ void k_zero_colmax() { g_colmax[threadIdx.x] = 0.f; }

__global__ void k_colmax(const float* __restrict__ contents) {
    int col = blockIdx.x * 256 + threadIdx.x;
    int r0  = blockIdx.y * 256;
    float m = 0.f;
    for (int r = 0; r < 256; r++)
        m = fmaxf(m, fabsf(contents[(size_t)(r0 + r) * HD + col]));
    atomicMax((int*)&g_colmax[col], __float_as_int(m));  // valid: values >= 0
}

__global__ void k_scale() {
    int h = threadIdx.x;
    g_scale[h] = fmaxf(g_colmax[h] / 127.0f, 1e-6f);
}

// ---------------- address row norms + bf16 normalized copy (float4) ----------------
__global__ void __launch_bounds__(256) k_addrnorm(const float* __restrict__ addresses) {
    __shared__ float wred[8];
    __shared__ float s_inv;
    int row = blockIdx.x, t = threadIdx.x;
    float4 v = ((const float4*)(addresses + (size_t)row * HD))[t];
    float ss = v.x * v.x + v.y * v.y + v.z * v.z + v.w * v.w;
#pragma unroll
    for (int s = 16; s > 0; s >>= 1) ss += __shfl_xor_sync(0xffffffffu, ss, s);
    if ((t & 31) == 0) wred[t >> 5] = ss;
    __syncthreads();
    if (t == 0) {
        float tot = 0.f;
#pragma unroll
        for (int i = 0; i < 8; i++) tot += wred[i];
        float n = fmaxf(sqrtf(tot), 1e-8f);
        s_inv = 1.0f / n;
        g_invn[row] = s_inv;
    }
    __syncthreads();
    float inv = s_inv;
    __nv_bfloat162* dst = (__nv_bfloat162*)(g_an_bf + (size_t)row * HD);
    dst[t * 2]     = __nv_bfloat162(__float2bfloat16(v.x * inv), __float2bfloat16(v.y * inv));
    dst[t * 2 + 1] = __nv_bfloat162(__float2bfloat16(v.z * inv), __float2bfloat16(v.w * inv));
}

// ---------------- query row norms (division: match jax rounding) ----------------
__global__ void __launch_bounds__(256) k_qnorm() {
    __shared__ float wred[8];
    __shared__ float s_n;
    int row = blockIdx.x, t = threadIdx.x;
    float4 v = ((const float4*)(g_query + (size_t)row * HD))[t];
    float ss = v.x * v.x + v.y * v.y + v.z * v.z + v.w * v.w;
#pragma unroll
    for (int s = 16; s > 0; s >>= 1) ss += __shfl_xor_sync(0xffffffffu, ss, s);
    if ((t & 31) == 0) wred[t >> 5] = ss;
    __syncthreads();
    if (t == 0) {
        float tot = 0.f;
#pragma unroll
        for (int i = 0; i < 8; i++) tot += wred[i];
        s_n = fmaxf(sqrtf(tot), 1e-8f);
    }
    __syncthreads();
    float n = s_n;
    float4 q = make_float4(v.x / n, v.y / n, v.z / n, v.w / n);
    ((float4*)(g_qn + (size_t)row * HD))[t] = q;
    __nv_bfloat162* dst = (__nv_bfloat162*)(g_qn_bf + (size_t)row * HD);
    dst[t * 2]     = __nv_bfloat162(__float2bfloat16(q.x), __float2bfloat16(q.y));
    dst[t * 2 + 1] = __nv_bfloat162(__float2bfloat16(q.z), __float2bfloat16(q.w));
}

// ---------------- fp32 tiled GEMM: C[m][n] = sum_k A[m][k] * B[n][k] ----------------
__device__ __forceinline__ void gemm_body(const float* __restrict__ A,
                                          const float* __restrict__ B,
                                          float* __restrict__ C,
                                          int Nn, int Kk) {
    __shared__ float sA[16][68];
    __shared__ float sB[16][68];
    const int tid = threadIdx.x;
    const int tx = tid % 16, ty = tid / 16;
    const int bm = blockIdx.y * 64, bn = blockIdx.x * 64;
    const int tk = tid % 16, tr = tid / 16;
    float acc[4][4];
#pragma unroll
    for (int i = 0; i < 4; i++)
#pragma unroll
        for (int j = 0; j < 4; j++) acc[i][j] = 0.f;

    for (int k0 = 0; k0 < Kk; k0 += 16) {
#pragma unroll
        for (int i = 0; i < 4; i++) {
            sA[tk][tr + i * 16] = A[(size_t)(bm + tr + i * 16) * Kk + k0 + tk];
            sB[tk][tr + i * 16] = B[(size_t)(bn + tr + i * 16) * Kk + k0 + tk];
        }
        __syncthreads();
#pragma unroll
        for (int kk = 0; kk < 16; kk++) {
            float4 a = *(const float4*)&sA[kk][ty * 4];
            float4 b = *(const float4*)&sB[kk][tx * 4];
            acc[0][0] += a.x * b.x; acc[0][1] += a.x * b.y; acc[0][2] += a.x * b.z; acc[0][3] += a.x * b.w;
            acc[1][0] += a.y * b.x; acc[1][1] += a.y * b.y; acc[1][2] += a.y * b.z; acc[1][3] += a.y * b.w;
            acc[2][0] += a.z * b.x; acc[2][1] += a.z * b.y; acc[2][2] += a.z * b.z; acc[2][3] += a.z * b.w;
            acc[3][0] += a.w * b.x; acc[3][1] += a.w * b.y; acc[3][2] += a.w * b.z; acc[3][3] += a.w * b.w;
        }
        __syncthreads();
    }
#pragma unroll
    for (int i = 0; i < 4; i++) {
        float4 o = make_float4(acc[i][0], acc[i][1], acc[i][2], acc[i][3]);
        *(float4*)&C[(size_t)(bm + ty * 4 + i) * Nn + bn + tx * 4] = o;
    }
}

__global__ void __launch_bounds__(256) k_gemm_query(const float* __restrict__ x,
                                                    const float* __restrict__ W) {
    gemm_body(x, W, g_query, HD, HD);
}
__global__ void __launch_bounds__(256) k_gemm_out(const float* __restrict__ W,
                                                  float* __restrict__ out) {
    gemm_body(g_read, W, out, HD, HD);
}

// ---------------- fused bf16 scores GEMM + per-half top-8 epilogue ----------------
// grid (16 mblocks [x, fastest], 512 nblocks [y]); 256 thr = 8 warps (4x2).
// BM=128 BN=128 BK=32, warp tile 32x64 via m16n8k16; cp.async double buffer.
__global__ void __launch_bounds__(256) k_scores_fused() {
    __shared__ __align__(16) __nv_bfloat16 sA[2][128][40];  // 40-half stride: conflict-free
    __shared__ __align__(16) __nv_bfloat16 sB[2][128][40];
    const int tid = threadIdx.x;
    const int warp = tid >> 5, lane = tid & 31;
    const int wm = warp >> 1, wn = warp & 1;
    const int g = lane >> 2, tg = lane & 3;
    const int m0 = blockIdx.x * 128;
    const int nblk = blockIdx.y;
    const int n0 = nblk * 128;

    const __nv_bfloat16* Ag = g_qn_bf + (size_t)m0 * HD;
    const __nv_bfloat16* Bg = g_an_bf + (size_t)n0 * HD;

    const int lr = tid >> 2;           // load row 0..63
    const int lc = (tid & 3) * 8;      // half offset within 32-wide K slab

    float acc[2][8][4];
#pragma unroll
    for (int mi = 0; mi < 2; mi++)
#pragma unroll
        for (int ni = 0; ni < 8; ni++)
#pragma unroll
            for (int r = 0; r < 4; r++) acc[mi][ni][r] = 0.f;

#define ISSUE(st, k0)                                                              \
    do {                                                                           \
        cp16(__cvta_generic_to_shared(&sA[st][lr][lc]),                            \
             Ag + (size_t)lr * HD + (k0) + lc);                                    \
        cp16(__cvta_generic_to_shared(&sA[st][lr + 64][lc]),                       \
             Ag + (size_t)(lr + 64) * HD + (k0) + lc);                             \
        cp16(__cvta_generic_to_shared(&sB[st][lr][lc]),                            \
             Bg + (size_t)lr * HD + (k0) + lc);                                    \
        cp16(__cvta_generic_to_shared(&sB[st][lr + 64][lc]),                       \
             Bg + (size_t)(lr + 64) * HD + (k0) + lc);                             \
    } while (0)

    ISSUE(0, 0);
    CP_COMMIT();

    for (int it = 0; it < 32; it++) {
        if (it < 31) {
            ISSUE((it + 1) & 1, (it + 1) * 32);
            CP_COMMIT();
            CP_WAIT(1);
        } else {
            CP_WAIT(0);
        }
        __syncthreads();

        const uint32_t* baseA = (const uint32_t*)&sA[it & 1][0][0];
        const uint32_t* baseB = (const uint32_t*)&sB[it & 1][0][0];
#pragma unroll
        for (int ks = 0; ks < 2; ks++) {
            const int kw = ks * 8;
            uint32_t afr[2][4];
#pragma unroll
            for (int mi = 0; mi < 2; mi++) {
                int w0 = (wm * 32 + mi * 16 + g) * 20 + kw + tg;
                afr[mi][0] = baseA[w0];
                afr[mi][1] = baseA[w0 + 160];
                afr[mi][2] = baseA[w0 + 4];
                afr[mi][3] = baseA[w0 + 164];
            }
            uint32_t bfr[8][2];
#pragma unroll
            for (int ni = 0; ni < 8; ni++) {
                int w0 = (wn * 64 + ni * 8 + g) * 20 + kw + tg;
                bfr[ni][0] = baseB[w0];
                bfr[ni][1] = baseB[w0 + 4];
            }
#pragma unroll
            for (int mi = 0; mi < 2; mi++)
#pragma unroll
                for (int ni = 0; ni < 8; ni++) {
                    asm volatile(
                        "mma.sync.aligned.m16n8k16.row.col.f32.bf16.bf16.f32 "
                        "{%0,%1,%2,%3}, {%4,%5,%6,%7}, {%8,%9}, {%0,%1,%2,%3};"
                        : "+f"(acc[mi][ni][0]), "+f"(acc[mi][ni][1]),
                          "+f"(acc[mi][ni][2]), "+f"(acc[mi][ni][3])
                        : "r"(afr[mi][0]), "r"(afr[mi][1]), "r"(afr[mi][2]), "r"(afr[mi][3]),
                          "r"(bfr[ni][0]), "r"(bfr[ni][1]));
                }
        }
        __syncthreads();
    }
#undef ISSUE

    // ---- epilogue: per output row, top-8 over this warp's 64 columns ----
    // Each lane owns 4 rows (mi x half), 16 cols each. Quad lanes (same g,
    // tg=0..3) share a row -> 2 shfl_xor merge rounds give top-8 of 64 cols.
#pragma unroll
    for (int rr = 0; rr < 4; rr++) {
        const int mi = rr >> 1, hl = (rr & 1) * 2;
        float v[8]; int id[8];
#pragma unroll
        for (int j = 0; j < 8; j++) { v[j] = -1e30f; id[j] = 0; }
#pragma unroll
        for (int ni = 0; ni < 8; ni++) {
#pragma unroll
            for (int c = 0; c < 2; c++) {
                float val = acc[mi][ni][hl + c];
                int col = n0 + wn * 64 + ni * 8 + tg * 2 + c;
                if (val > v[7]) {
                    v[7] = val; id[7] = col;
#pragma unroll
                    for (int j = 7; j > 0; j--) {
                        if (v[j] > v[j - 1]) {
                            float fv = v[j]; v[j] = v[j - 1]; v[j - 1] = fv;
                            int   fi = id[j]; id[j] = id[j - 1]; id[j - 1] = fi;
                        }
                    }
                }
            }
        }
#pragma unroll
        for (int st = 1; st <= 2; st <<= 1) {
            float ov[8]; int oi[8];
#pragma unroll
            for (int j = 0; j < 8; j++) {
                ov[j] = __shfl_xor_sync(0xffffffffu, v[j], st);
                oi[j] = __shfl_xor_sync(0xffffffffu, id[j], st);
            }
            float mv[8]; int mid[8];
            int a = 0, b = 0;
#pragma unroll
            for (int j = 0; j < 8; j++) {
                bool ta = (b >= 8) || (a < 8 && v[a] >= ov[b]);
                mv[j]  = ta ? v[a]  : ov[b];
                mid[j] = ta ? id[a] : oi[b];
                if (ta) a++; else b++;
            }
#pragma unroll
            for (int j = 0; j < 8; j++) { v[j] = mv[j]; id[j] = mid[j]; }
        }
        if (tg == 0) {
            int row = m0 + wm * 32 + mi * 16 + (rr & 1) * 8 + g;
            size_t base = ((size_t)row * NBLK + nblk) * PART_PER_BLK + wn * 8;
#pragma unroll
            for (int j = 0; j < 8; j++) { g_pv[base + j] = v[j]; g_pi[base + j] = id[j]; }
        }
    }
}

// ---------------- merge partial top-8 lists -> top-32 candidates per query ----------------
__global__ void __launch_bounds__(256) k_merge() {
    __shared__ float sval[2048];
    __shared__ int   sidx[2048];
    __shared__ float rv[256];
    __shared__ int   rp[256];
    const int q = blockIdx.x, t = threadIdx.x;
    const float* pv = g_pv + (size_t)q * NBLK * PART_PER_BLK;   // 8192 entries
    const int*   pi = g_pi + (size_t)q * NBLK * PART_PER_BLK;

    float tv[8]; int ti[8];
#pragma unroll
    for (int j = 0; j < 8; j++) { tv[j] = -1e30f; ti[j] = 0; }

    for (int i = 0; i < 32; i++) {
        int e = i * 256 + t;
        float v = pv[e];
        if (v > tv[7]) {
            int idx = pi[e];
            tv[7] = v; ti[7] = idx;
#pragma unroll
            for (int j = 7; j > 0; j--) {
                if (tv[j] > tv[j - 1]) {
                    float fv = tv[j]; tv[j] = tv[j - 1]; tv[j - 1] = fv;
                    int   fi = ti[j]; ti[j] = ti[j - 1]; ti[j - 1] = fi;
                }
            }
        }
    }
#pragma unroll
    for (int j = 0; j < 8; j++) { sval[t * 8 + j] = tv[j]; sidx[t * 8 + j] = ti[j]; }
    __syncthreads();

    for (int r = 0; r < MCAND; r++) {
        float bv = -1e30f; int bp = 0;
#pragma unroll
        for (int j = 0; j < 8; j++) {
            float v = sval[t * 8 + j];
            if (v > bv) { bv = v; bp = t * 8 + j; }
        }
        rv[t] = bv; rp[t] = bp;
        __syncthreads();
        for (int s = 128; s > 0; s >>= 1) {
            if (t < s && rv[t + s] > rv[t]) { rv[t] = rv[t + s]; rp[t] = rp[t + s]; }
            __syncthreads();
        }
        if (t == 0) { g_cand[q * MCAND + r] = sidx[rp[0]]; sval[rp[0]] = -1e30f; }
        __syncthreads();
    }
}

// ---------------- exact fp32 rescore + top-8 + softmax + dequant gather ----------------
__global__ void __launch_bounds__(256) k_rescore(const float* __restrict__ addresses,
                                                 const float* __restrict__ contents) {
    __shared__ float qrow[HD];
    __shared__ float red[256];
    __shared__ float cs[MCAND];
    __shared__ float w8[TOPK];
    __shared__ int   i8[TOPK];
    const int q = blockIdx.x, t = threadIdx.x;

#pragma unroll
    for (int i = 0; i < 4; i++) qrow[t + i * 256] = g_qn[(size_t)q * HD + t + i * 256];
    __syncthreads();

    for (int c = 0; c < MCAND; c++) {
        int idx = g_cand[q * MCAND + c];
        const float* arow = addresses + (size_t)idx * HD;
        float p = 0.f;
#pragma unroll
        for (int i = 0; i < 4; i++) { int h = t + i * 256; p += qrow[h] * arow[h]; }
        red[t] = p; __syncthreads();
        for (int s = 128; s > 0; s >>= 1) { if (t < s) red[t] += red[t + s]; __syncthreads(); }
        if (t == 0) cs[c] = red[0] * g_invn[idx];
        __syncthreads();
    }

    if (t == 0) {
        float kv[TOPK];
        for (int j = 0; j < TOPK; j++) {
            float bv = -1e30f; int bc = 0;
            for (int c = 0; c < MCAND; c++)
                if (cs[c] > bv) { bv = cs[c]; bc = c; }
            kv[j] = bv; i8[j] = g_cand[q * MCAND + bc]; cs[bc] = -1e30f;
        }
        float mx = kv[0];
        float e[TOPK]; float ssum = 0.f;
        for (int j = 0; j < TOPK; j++) { e[j] = expf(kv[j] - mx); ssum += e[j]; }
        for (int j = 0; j < TOPK; j++) w8[j] = e[j] / ssum;
    }
    __syncthreads();

#pragma unroll
    for (int i = 0; i < 4; i++) {
        int h = t + i * 256;
        float sc = g_scale[h];
        float a = 0.f;
#pragma unroll
        for (int j = 0; j < TOPK; j++) {
            float v = contents[(size_t)i8[j] * HD + h];
            float qq = rintf(v / sc);
            qq = fminf(fmaxf(qq, -127.f), 127.f);
            a += w8[j] * (qq * sc);
        }
        g_read[(size_t)q * HD + h] = a;
    }
}

// ---------------- launch ----------------
extern "C" void kernel_launch(void* const* d_in, const int* in_sizes, int n_in,
                              void* d_out, int out_size) {
    const float* x         = (const float*)d_in[0];
    const float* addresses = (const float*)d_in[1];
    const float* contents  = (const float*)d_in[2];
    const float* W_addr    = (const float*)d_in[3];
    const float* W_read    = (const float*)d_in[4];
    float* out = (float*)d_out;

    k_zero_colmax<<<1, HD>>>();
    k_colmax<<<dim3(HD / 256, NS / 256), 256>>>(contents);
    k_scale<<<1, HD>>>();
    k_addrnorm<<<NS, 256>>>(addresses);
    k_gemm_query<<<dim3(HD / 64, BS / 64), 256>>>(x, W_addr);
    k_qnorm<<<BS, 256>>>();
    k_scores_fused<<<dim3(BS / 128, NBLK), 256>>>();   // m fastest: B read once from DRAM
    k_merge<<<BS, 256>>>();
    k_rescore<<<BS, 256>>>(addresses, contents);
    k_gemm_out<<<dim3(HD / 64, BS / 64), 256>>>(W_read, out);
}